// round 1
// baseline (speedup 1.0000x reference)
#include <cuda_runtime.h>
#include <math.h>

#define B 2
#define S 2048
#define E 768
#define H 12
#define D 64
#define BSZ (B*S)              // 4096 rows
#define QKV_ELEMS (B*H*S*D)    // 3,145,728

// Scratch (allocation-free rule: device globals)
__device__ float g_Q[QKV_ELEMS];
__device__ float g_K[QKV_ELEMS];
__device__ float g_V[QKV_ELEMS];
__device__ float g_att[BSZ*E];
__device__ float g_maskadd[BSZ];

// ---------------------------------------------------------------------------
// Mask normalization: detect whether mask buffer is u8 / int32 / float32 and
// produce additive mask (0 for keep, -1e30 for masked-out).
// ---------------------------------------------------------------------------
__global__ void mask_prep_kernel(const unsigned char* __restrict__ m)
{
    __shared__ int cls[4];
    int tid = threadIdx.x;
    if (tid < 4) cls[tid] = 0;
    __syncthreads();
    for (int i = tid; i < BSZ; i += blockDim.x)
        if (m[i]) atomicAdd(&cls[i & 3], 1);
    __syncthreads();
    int mode = 0;                                   // 0 = u8
    if (cls[1] == 0 && cls[2] == 0 && cls[3] == 0) mode = 1;   // int32 0/1
    else if (cls[0] == 0 && cls[1] == 0)            mode = 2;  // float32 0/1
    for (int i = tid; i < BSZ; i += blockDim.x) {
        bool v;
        if (mode == 1)      v = ((const int*)m)[i] != 0;
        else if (mode == 2) v = ((const float*)m)[i] != 0.0f;
        else                v = m[i] != 0;
        g_maskadd[i] = v ? 0.0f : -1e30f;
    }
}

// ---------------------------------------------------------------------------
// QKV projection GEMM: out[m,n] = sum_k X[m,k]*W[n,k] + bias[n]
// Fused RoPE (interleaved, theta=10000) for Q,K and transpose to [B,H,S,D].
// Tiles 128x128x8, 256 threads, 8x8 per thread.
// ---------------------------------------------------------------------------
#define TBM 128
#define TBN 128
#define TBK 8

__global__ __launch_bounds__(256)
void qkv_kernel(const float* __restrict__ Xq, const float* __restrict__ Xk,
                const float* __restrict__ Xv,
                const float* __restrict__ Wq, const float* __restrict__ Wk,
                const float* __restrict__ Wv,
                const float* __restrict__ bq, const float* __restrict__ bk,
                const float* __restrict__ bv)
{
    const int z = blockIdx.z;
    const float* X    = (z == 0) ? Xq : (z == 1) ? Xk : Xv;
    const float* W    = (z == 0) ? Wq : (z == 1) ? Wk : Wv;
    const float* bias = (z == 0) ? bq : (z == 1) ? bk : bv;
    float* out        = (z == 0) ? g_Q : (z == 1) ? g_K : g_V;
    const bool do_rope = (z < 2);

    __shared__ float As[TBK][TBM + 4];
    __shared__ float Bs[TBK][TBN + 4];

    const int tid = threadIdx.x;
    const int m0 = blockIdx.y * TBM;
    const int n0 = blockIdx.x * TBN;

    const int rr = (tid / 16) * 8;
    const int cc = (tid % 16) * 8;

    float acc[8][8];
    #pragma unroll
    for (int i = 0; i < 8; i++)
        #pragma unroll
        for (int j = 0; j < 8; j++) acc[i][j] = 0.0f;

    const int loadRow = tid >> 1;          // 0..127
    const int loadK   = (tid & 1) * 4;

    const float* Aptr = X + (size_t)(m0 + loadRow) * E + loadK;
    const float* Bptr = W + (size_t)(n0 + loadRow) * E + loadK;

    for (int k0 = 0; k0 < E; k0 += TBK) {
        float4 av  = *(const float4*)(Aptr + k0);
        float4 bv4 = *(const float4*)(Bptr + k0);
        As[loadK + 0][loadRow] = av.x;  As[loadK + 1][loadRow] = av.y;
        As[loadK + 2][loadRow] = av.z;  As[loadK + 3][loadRow] = av.w;
        Bs[loadK + 0][loadRow] = bv4.x; Bs[loadK + 1][loadRow] = bv4.y;
        Bs[loadK + 2][loadRow] = bv4.z; Bs[loadK + 3][loadRow] = bv4.w;
        __syncthreads();
        #pragma unroll
        for (int kk = 0; kk < TBK; kk++) {
            float a[8], bb[8];
            #pragma unroll
            for (int i = 0; i < 8; i++) a[i]  = As[kk][rr + i];
            #pragma unroll
            for (int j = 0; j < 8; j++) bb[j] = Bs[kk][cc + j];
            #pragma unroll
            for (int i = 0; i < 8; i++)
                #pragma unroll
                for (int j = 0; j < 8; j++)
                    acc[i][j] += a[i] * bb[j];
        }
        __syncthreads();
    }

    const float LN1E4 = 9.210340371976184f;   // ln(10000)
    #pragma unroll
    for (int i = 0; i < 8; i++) {
        const int m = m0 + rr + i;
        const int bb = m / S;
        const int s  = m % S;
        #pragma unroll
        for (int j = 0; j < 8; j += 2) {
            const int n = n0 + cc + j;
            const int h = n / D;
            const int d = n % D;
            float v0 = acc[i][j]     + bias[n];
            float v1 = acc[i][j + 1] + bias[n + 1];
            if (do_rope) {
                const int pi = d >> 1;
                float invf = expf(-((float)(2 * pi) / (float)D) * LN1E4);
                float f = (float)s * invf;
                float sn, cs;
                sincosf(f, &sn, &cs);
                float r0 = v0 * cs - v1 * sn;
                float r1 = v1 * cs + v0 * sn;
                v0 = r0; v1 = r1;
            }
            const int idx = (((bb * H + h) * S + s) * D + d);
            out[idx]     = v0;
            out[idx + 1] = v1;
        }
    }
}

// ---------------------------------------------------------------------------
// Flash attention: per (b,h,q-tile of 64). K/V tiles of 64, online softmax.
// 256 threads: thread (tid/16, tid%16) owns a 4x4 fragment.
// ---------------------------------------------------------------------------
#define QT 64
#define KT 64
#define SPAD 68    // 64 + 4, keeps float4 alignment (68*4B = 272B = 17*16B)

__global__ __launch_bounds__(256)
void attn_kernel(const float* __restrict__ pb, const float* __restrict__ coeff)
{
    extern __shared__ float sm[];
    float (*Qs)[SPAD] = (float(*)[SPAD])(sm);                 // [d][q]
    float (*Ks)[SPAD] = (float(*)[SPAD])(sm + 64 * SPAD);     // [d][k]
    float (*Vs)[SPAD] = (float(*)[SPAD])(sm + 2 * 64 * SPAD); // [k][d]
    float (*Ps)[SPAD] = (float(*)[SPAD])(sm + 3 * 64 * SPAD); // [k][q]

    const int b  = blockIdx.z;
    const int h  = blockIdx.y;
    const int q0 = blockIdx.x * QT;

    const float* Qg = g_Q + (size_t)((b * H + h) * S) * D;
    const float* Kg = g_K + (size_t)((b * H + h) * S) * D;
    const float* Vg = g_V + (size_t)((b * H + h) * S) * D;

    const int tid = threadIdx.x;
    const int r0 = (tid / 16) * 4;   // q-row fragment base
    const int c0 = (tid % 16) * 4;   // col fragment base (k for S, d for O)

    const float coeff_h = coeff[h];

    // Load Q tile transposed: Qs[d][q]
    {
        const int q = tid >> 2;
        const int dbase = (tid & 3) * 16;
        #pragma unroll
        for (int t = 0; t < 4; t++) {
            float4 v = *(const float4*)(Qg + (size_t)(q0 + q) * D + dbase + 4 * t);
            Qs[dbase + 4 * t + 0][q] = v.x;
            Qs[dbase + 4 * t + 1][q] = v.y;
            Qs[dbase + 4 * t + 2][q] = v.z;
            Qs[dbase + 4 * t + 3][q] = v.w;
        }
    }
    __syncthreads();

    float pbq[4];
    #pragma unroll
    for (int i = 0; i < 4; i++) pbq[i] = pb[b * S + q0 + r0 + i];

    float m_i[4], l_i[4], o[4][4];
    #pragma unroll
    for (int i = 0; i < 4; i++) {
        m_i[i] = -1e30f; l_i[i] = 0.0f;
        #pragma unroll
        for (int j = 0; j < 4; j++) o[i][j] = 0.0f;
    }

    for (int k0 = 0; k0 < S; k0 += KT) {
        // Load K (transposed) and V (direct) tiles
        {
            const int r = tid >> 2;
            const int dbase = (tid & 3) * 16;
            #pragma unroll
            for (int t = 0; t < 4; t++) {
                float4 kv = *(const float4*)(Kg + (size_t)(k0 + r) * D + dbase + 4 * t);
                Ks[dbase + 4 * t + 0][r] = kv.x;
                Ks[dbase + 4 * t + 1][r] = kv.y;
                Ks[dbase + 4 * t + 2][r] = kv.z;
                Ks[dbase + 4 * t + 3][r] = kv.w;
                float4 vv = *(const float4*)(Vg + (size_t)(k0 + r) * D + dbase + 4 * t);
                *(float4*)&Vs[r][dbase + 4 * t] = vv;
            }
        }
        __syncthreads();

        // S = Q K^T fragment
        float sc[4][4];
        #pragma unroll
        for (int i = 0; i < 4; i++)
            #pragma unroll
            for (int j = 0; j < 4; j++) sc[i][j] = 0.0f;

        #pragma unroll 8
        for (int kk = 0; kk < D; kk++) {
            float4 a = *(const float4*)&Qs[kk][r0];
            float4 bv = *(const float4*)&Ks[kk][c0];
            float af[4] = {a.x, a.y, a.z, a.w};
            float bf[4] = {bv.x, bv.y, bv.z, bv.w};
            #pragma unroll
            for (int i = 0; i < 4; i++)
                #pragma unroll
                for (int j = 0; j < 4; j++)
                    sc[i][j] += af[i] * bf[j];
        }

        // score = sc/8 + coeff*(pbq - pbk) + maskadd
        float colb[4];
        #pragma unroll
        for (int j = 0; j < 4; j++) {
            int kidx = b * S + k0 + c0 + j;
            colb[j] = -coeff_h * pb[kidx] + g_maskadd[kidx];
        }
        #pragma unroll
        for (int i = 0; i < 4; i++) {
            float rowb = coeff_h * pbq[i];
            #pragma unroll
            for (int j = 0; j < 4; j++)
                sc[i][j] = sc[i][j] * 0.125f + rowb + colb[j];
        }

        // Online softmax (row reductions across the 16-lane row group)
        #pragma unroll
        for (int i = 0; i < 4; i++) {
            float tmax = fmaxf(fmaxf(sc[i][0], sc[i][1]), fmaxf(sc[i][2], sc[i][3]));
            #pragma unroll
            for (int off = 8; off >= 1; off >>= 1)
                tmax = fmaxf(tmax, __shfl_xor_sync(0xffffffffu, tmax, off));
            float mnew = fmaxf(m_i[i], tmax);
            float p[4], psum = 0.0f;
            #pragma unroll
            for (int j = 0; j < 4; j++) { p[j] = __expf(sc[i][j] - mnew); psum += p[j]; }
            #pragma unroll
            for (int off = 8; off >= 1; off >>= 1)
                psum += __shfl_xor_sync(0xffffffffu, psum, off);
            float scale = __expf(m_i[i] - mnew);
            l_i[i] = l_i[i] * scale + psum;
            m_i[i] = mnew;
            #pragma unroll
            for (int j = 0; j < 4; j++) o[i][j] *= scale;
            #pragma unroll
            for (int j = 0; j < 4; j++) Ps[c0 + j][r0 + i] = p[j];
        }
        __syncthreads();

        // O += P V
        #pragma unroll 8
        for (int kk = 0; kk < KT; kk++) {
            float4 a = *(const float4*)&Ps[kk][r0];
            float4 bv = *(const float4*)&Vs[kk][c0];
            float af[4] = {a.x, a.y, a.z, a.w};
            float bf[4] = {bv.x, bv.y, bv.z, bv.w};
            #pragma unroll
            for (int i = 0; i < 4; i++)
                #pragma unroll
                for (int j = 0; j < 4; j++)
                    o[i][j] += af[i] * bf[j];
        }
        __syncthreads();
    }

    // Normalize and store to [B,S,E]
    #pragma unroll
    for (int i = 0; i < 4; i++) {
        float inv = 1.0f / l_i[i];
        int srow = q0 + r0 + i;
        #pragma unroll
        for (int j = 0; j < 4; j++)
            g_att[(size_t)(b * S + srow) * E + h * D + c0 + j] = o[i][j] * inv;
    }
}

// ---------------------------------------------------------------------------
// Output projection: d_out[m,n] = sum_k g_att[m,k]*fc_w[n,k] + fc_b[n]
// ---------------------------------------------------------------------------
__global__ __launch_bounds__(256)
void oproj_kernel(const float* __restrict__ W, const float* __restrict__ bias,
                  float* __restrict__ out)
{
    __shared__ float As[TBK][TBM + 4];
    __shared__ float Bs[TBK][TBN + 4];

    const int tid = threadIdx.x;
    const int m0 = blockIdx.y * TBM;
    const int n0 = blockIdx.x * TBN;
    const int rr = (tid / 16) * 8;
    const int cc = (tid % 16) * 8;

    float acc[8][8];
    #pragma unroll
    for (int i = 0; i < 8; i++)
        #pragma unroll
        for (int j = 0; j < 8; j++) acc[i][j] = 0.0f;

    const int loadRow = tid >> 1;
    const int loadK   = (tid & 1) * 4;

    const float* Aptr = g_att + (size_t)(m0 + loadRow) * E + loadK;
    const float* Bptr = W + (size_t)(n0 + loadRow) * E + loadK;

    for (int k0 = 0; k0 < E; k0 += TBK) {
        float4 av  = *(const float4*)(Aptr + k0);
        float4 bv4 = *(const float4*)(Bptr + k0);
        As[loadK + 0][loadRow] = av.x;  As[loadK + 1][loadRow] = av.y;
        As[loadK + 2][loadRow] = av.z;  As[loadK + 3][loadRow] = av.w;
        Bs[loadK + 0][loadRow] = bv4.x; Bs[loadK + 1][loadRow] = bv4.y;
        Bs[loadK + 2][loadRow] = bv4.z; Bs[loadK + 3][loadRow] = bv4.w;
        __syncthreads();
        #pragma unroll
        for (int kk = 0; kk < TBK; kk++) {
            float a[8], bb[8];
            #pragma unroll
            for (int i = 0; i < 8; i++) a[i]  = As[kk][rr + i];
            #pragma unroll
            for (int j = 0; j < 8; j++) bb[j] = Bs[kk][cc + j];
            #pragma unroll
            for (int i = 0; i < 8; i++)
                #pragma unroll
                for (int j = 0; j < 8; j++)
                    acc[i][j] += a[i] * bb[j];
        }
        __syncthreads();
    }

    #pragma unroll
    for (int i = 0; i < 8; i++) {
        const int m = m0 + rr + i;
        #pragma unroll
        for (int j = 0; j < 8; j++) {
            const int n = n0 + cc + j;
            out[(size_t)m * E + n] = acc[i][j] + bias[n];
        }
    }
}

// ---------------------------------------------------------------------------
extern "C" void kernel_launch(void* const* d_in, const int* in_sizes, int n_in,
                              void* d_out, int out_size)
{
    const float* query = (const float*)d_in[0];
    const float* key   = (const float*)d_in[1];
    const float* value = (const float*)d_in[2];
    const float* pb    = (const float*)d_in[3];
    const unsigned char* mask = (const unsigned char*)d_in[4];
    const float* wq_w = (const float*)d_in[5];
    const float* wq_b = (const float*)d_in[6];
    const float* wk_w = (const float*)d_in[7];
    const float* wk_b = (const float*)d_in[8];
    const float* wv_w = (const float*)d_in[9];
    const float* wv_b = (const float*)d_in[10];
    const float* fc_w = (const float*)d_in[11];
    const float* fc_b = (const float*)d_in[12];
    const float* coeff = (const float*)d_in[13];
    float* out = (float*)d_out;

    const int attn_smem = 4 * 64 * SPAD * (int)sizeof(float);  // 69,632 B
    cudaFuncSetAttribute(attn_kernel,
                         cudaFuncAttributeMaxDynamicSharedMemorySize, attn_smem);

    mask_prep_kernel<<<1, 256>>>(mask);

    dim3 g1(E / TBN, BSZ / TBM, 3);   // (6, 32, 3)
    qkv_kernel<<<g1, 256>>>(query, key, value, wq_w, wk_w, wv_w, wq_b, wk_b, wv_b);

    dim3 g2(S / QT, H, B);            // (32, 12, 2)
    attn_kernel<<<g2, 256, attn_smem>>>(pb, coeff);

    dim3 g3(E / TBN, BSZ / TBM);      // (6, 32)
    oproj_kernel<<<g3, 256>>>(fc_w, fc_b, out);
}

// round 3
// speedup vs baseline: 1.4368x; 1.4368x over previous
#include <cuda_runtime.h>
#include <math.h>

#define B 2
#define S 2048
#define E 768
#define H 12
#define D 64
#define BSZ (B*S)
#define QKV_ELEMS (B*H*S*D)

// Scratch (allocation-free rule: device globals)
__device__ float g_Q[QKV_ELEMS];
__device__ float g_K[QKV_ELEMS];
__device__ float g_V[QKV_ELEMS];
__device__ float g_att[BSZ*E];
__device__ float g_maskadd[BSZ];
__device__ float g_kbias[B*H*S];

// ---------------------------------------------------------------------------
// helpers
// ---------------------------------------------------------------------------
__device__ __forceinline__ unsigned f2tf(float f) {
    unsigned u;
    asm("cvt.rna.tf32.f32 %0, %1;" : "=r"(u) : "f"(f));
    return u;
}
// 3xTF32 operand split: x ~= hi + lo, both tf32 (hi: top 11 bits, lo: next 11)
__device__ __forceinline__ void splt(float f, unsigned& hi, unsigned& lo) {
    hi = f2tf(f);
    lo = f2tf(f - __uint_as_float(hi));
}

// D(16x8,f32) += A(16x8,tf32,row) * B(8x8,tf32,col)
__device__ __forceinline__ void mma8(float* c, const unsigned* a,
                                     unsigned b0, unsigned b1) {
    asm volatile(
        "mma.sync.aligned.m16n8k8.row.col.f32.tf32.tf32.f32 "
        "{%0,%1,%2,%3},{%4,%5,%6,%7},{%8,%9},{%0,%1,%2,%3};"
        : "+f"(c[0]), "+f"(c[1]), "+f"(c[2]), "+f"(c[3])
        : "r"(a[0]), "r"(a[1]), "r"(a[2]), "r"(a[3]), "r"(b0), "r"(b1));
}

// ---------------------------------------------------------------------------
// Mask normalization (dtype-agnostic) -> g_maskadd
// ---------------------------------------------------------------------------
__global__ void mask_prep_kernel(const unsigned char* __restrict__ m)
{
    __shared__ int cls[4];
    int tid = threadIdx.x;
    if (tid < 4) cls[tid] = 0;
    __syncthreads();
    for (int i = tid; i < BSZ; i += blockDim.x)
        if (m[i]) atomicAdd(&cls[i & 3], 1);
    __syncthreads();
    int mode = 0;                                              // u8
    if (cls[1] == 0 && cls[2] == 0 && cls[3] == 0) mode = 1;   // int32 0/1
    else if (cls[0] == 0 && cls[1] == 0)           mode = 2;   // float32 0/1
    for (int i = tid; i < BSZ; i += blockDim.x) {
        bool v;
        if (mode == 1)      v = ((const int*)m)[i] != 0;
        else if (mode == 2) v = ((const float*)m)[i] != 0.0f;
        else                v = m[i] != 0;
        g_maskadd[i] = v ? 0.0f : -1e30f;
    }
}

// per-(b,h,k) additive column bias: -coeff[h]*pb[b,k] + maskadd[b,k]
__global__ void kbias_kernel(const float* __restrict__ pb,
                             const float* __restrict__ coeff)
{
    int idx = blockIdx.x * 256 + threadIdx.x;
    int bh = idx / S, k = idx - bh * S;
    int b = bh / H, h = bh - b * H;
    g_kbias[idx] = -coeff[h] * pb[b * S + k] + g_maskadd[b * S + k];
}

// ---------------------------------------------------------------------------
// QKV projection, 3xTF32. CTA 128x128, 8 warps (64x32 each).
// Fused bias + RoPE + transpose to [B,H,S,D].
// ---------------------------------------------------------------------------
__global__ __launch_bounds__(256)
void qkv_kernel(const float* __restrict__ Xq, const float* __restrict__ Xk,
                const float* __restrict__ Xv,
                const float* __restrict__ Wq, const float* __restrict__ Wk,
                const float* __restrict__ Wv,
                const float* __restrict__ bq, const float* __restrict__ bk,
                const float* __restrict__ bv)
{
    const int z = blockIdx.z;
    const float* X    = (z == 0) ? Xq : (z == 1) ? Xk : Xv;
    const float* W    = (z == 0) ? Wq : (z == 1) ? Wk : Wv;
    const float* bias = (z == 0) ? bq : (z == 1) ? bk : bv;
    float* out        = (z == 0) ? g_Q : (z == 1) ? g_K : g_V;
    const bool rope = (z < 2);

    __shared__ unsigned As[2][128][20];   // [plane][row][k] hi/lo
    __shared__ unsigned Bs[2][128][20];

    const int tid = threadIdx.x;
    const int w = tid >> 5, wm = w >> 2, wn = w & 3;
    const int lane = tid & 31, g = lane >> 2, tig = lane & 3;
    const int m0 = blockIdx.y * 128, n0 = blockIdx.x * 128;

    float acc[4][4][4];
    #pragma unroll
    for (int a = 0; a < 4; a++)
        #pragma unroll
        for (int b2 = 0; b2 < 4; b2++)
            #pragma unroll
            for (int c = 0; c < 4; c++) acc[a][b2][c] = 0.0f;

    for (int k0 = 0; k0 < E; k0 += 16) {
        #pragma unroll
        for (int t = 0; t < 2; t++) {
            int i = tid + t * 256;
            int r = i >> 2, c4 = (i & 3) << 2;
            float4 av = *(const float4*)(X + (size_t)(m0 + r) * E + k0 + c4);
            splt(av.x, As[0][r][c4 + 0], As[1][r][c4 + 0]);
            splt(av.y, As[0][r][c4 + 1], As[1][r][c4 + 1]);
            splt(av.z, As[0][r][c4 + 2], As[1][r][c4 + 2]);
            splt(av.w, As[0][r][c4 + 3], As[1][r][c4 + 3]);
            float4 bv4 = *(const float4*)(W + (size_t)(n0 + r) * E + k0 + c4);
            splt(bv4.x, Bs[0][r][c4 + 0], Bs[1][r][c4 + 0]);
            splt(bv4.y, Bs[0][r][c4 + 1], Bs[1][r][c4 + 1]);
            splt(bv4.z, Bs[0][r][c4 + 2], Bs[1][r][c4 + 2]);
            splt(bv4.w, Bs[0][r][c4 + 3], Bs[1][r][c4 + 3]);
        }
        __syncthreads();
        #pragma unroll
        for (int kk = 0; kk < 16; kk += 8) {
            unsigned af[2][4][4], bf[2][4][2];
            #pragma unroll
            for (int fm = 0; fm < 4; fm++) {
                int rb = wm * 64 + fm * 16 + g;
                #pragma unroll
                for (int p = 0; p < 2; p++) {
                    af[p][fm][0] = As[p][rb][kk + tig];
                    af[p][fm][1] = As[p][rb + 8][kk + tig];
                    af[p][fm][2] = As[p][rb][kk + tig + 4];
                    af[p][fm][3] = As[p][rb + 8][kk + tig + 4];
                }
            }
            #pragma unroll
            for (int fn = 0; fn < 4; fn++) {
                int cb = wn * 32 + fn * 8 + g;
                #pragma unroll
                for (int p = 0; p < 2; p++) {
                    bf[p][fn][0] = Bs[p][cb][kk + tig];
                    bf[p][fn][1] = Bs[p][cb][kk + tig + 4];
                }
            }
            #pragma unroll
            for (int fm = 0; fm < 4; fm++)
                #pragma unroll
                for (int fn = 0; fn < 4; fn++) {
                    mma8(acc[fm][fn], af[0][fm], bf[0][fn][0], bf[0][fn][1]);
                    mma8(acc[fm][fn], af[1][fm], bf[0][fn][0], bf[0][fn][1]);
                    mma8(acc[fm][fn], af[0][fm], bf[1][fn][0], bf[1][fn][1]);
                }
        }
        __syncthreads();
    }

    // epilogue: bias + RoPE + transpose to [B,H,S,D]
    #pragma unroll
    for (int fn = 0; fn < 4; fn++) {
        const int col = n0 + wn * 32 + fn * 8 + 2 * tig;   // even
        const int h = col / D, d = col % D;
        const float b0v = bias[col], b1v = bias[col + 1];
        const float invf = rope
            ? exp2f(-(float)d * (13.287712379549449f / 64.0f)) : 0.0f;
        #pragma unroll
        for (int fm = 0; fm < 4; fm++) {
            const int row = m0 + wm * 64 + fm * 16 + g;
            #pragma unroll
            for (int half = 0; half < 2; half++) {
                const int r = row + half * 8;
                const int bb = r >> 11, s = r & 2047;
                float v0 = acc[fm][fn][half * 2 + 0] + b0v;
                float v1 = acc[fm][fn][half * 2 + 1] + b1v;
                if (rope) {
                    float sn, cs;
                    sincosf((float)s * invf, &sn, &cs);
                    float t0 = v0 * cs - v1 * sn;
                    v1 = v1 * cs + v0 * sn;
                    v0 = t0;
                }
                *(float2*)&out[(((size_t)bb * H + h) * S + s) * D + d] =
                    make_float2(v0, v1);
            }
        }
    }
}

// ---------------------------------------------------------------------------
// Output projection: d_out = g_att @ fc_w^T + fc_b  (3xTF32)
// ---------------------------------------------------------------------------
__global__ __launch_bounds__(256)
void oproj_kernel(const float* __restrict__ Wf, const float* __restrict__ bias,
                  float* __restrict__ out)
{
    __shared__ unsigned As[2][128][20];
    __shared__ unsigned Bs[2][128][20];

    const int tid = threadIdx.x;
    const int w = tid >> 5, wm = w >> 2, wn = w & 3;
    const int lane = tid & 31, g = lane >> 2, tig = lane & 3;
    const int m0 = blockIdx.y * 128, n0 = blockIdx.x * 128;

    float acc[4][4][4];
    #pragma unroll
    for (int a = 0; a < 4; a++)
        #pragma unroll
        for (int b2 = 0; b2 < 4; b2++)
            #pragma unroll
            for (int c = 0; c < 4; c++) acc[a][b2][c] = 0.0f;

    for (int k0 = 0; k0 < E; k0 += 16) {
        #pragma unroll
        for (int t = 0; t < 2; t++) {
            int i = tid + t * 256;
            int r = i >> 2, c4 = (i & 3) << 2;
            float4 av = *(const float4*)(g_att + (size_t)(m0 + r) * E + k0 + c4);
            splt(av.x, As[0][r][c4 + 0], As[1][r][c4 + 0]);
            splt(av.y, As[0][r][c4 + 1], As[1][r][c4 + 1]);
            splt(av.z, As[0][r][c4 + 2], As[1][r][c4 + 2]);
            splt(av.w, As[0][r][c4 + 3], As[1][r][c4 + 3]);
            float4 bv4 = *(const float4*)(Wf + (size_t)(n0 + r) * E + k0 + c4);
            splt(bv4.x, Bs[0][r][c4 + 0], Bs[1][r][c4 + 0]);
            splt(bv4.y, Bs[0][r][c4 + 1], Bs[1][r][c4 + 1]);
            splt(bv4.z, Bs[0][r][c4 + 2], Bs[1][r][c4 + 2]);
            splt(bv4.w, Bs[0][r][c4 + 3], Bs[1][r][c4 + 3]);
        }
        __syncthreads();
        #pragma unroll
        for (int kk = 0; kk < 16; kk += 8) {
            unsigned af[2][4][4], bf[2][4][2];
            #pragma unroll
            for (int fm = 0; fm < 4; fm++) {
                int rb = wm * 64 + fm * 16 + g;
                #pragma unroll
                for (int p = 0; p < 2; p++) {
                    af[p][fm][0] = As[p][rb][kk + tig];
                    af[p][fm][1] = As[p][rb + 8][kk + tig];
                    af[p][fm][2] = As[p][rb][kk + tig + 4];
                    af[p][fm][3] = As[p][rb + 8][kk + tig + 4];
                }
            }
            #pragma unroll
            for (int fn = 0; fn < 4; fn++) {
                int cb = wn * 32 + fn * 8 + g;
                #pragma unroll
                for (int p = 0; p < 2; p++) {
                    bf[p][fn][0] = Bs[p][cb][kk + tig];
                    bf[p][fn][1] = Bs[p][cb][kk + tig + 4];
                }
            }
            #pragma unroll
            for (int fm = 0; fm < 4; fm++)
                #pragma unroll
                for (int fn = 0; fn < 4; fn++) {
                    mma8(acc[fm][fn], af[0][fm], bf[0][fn][0], bf[0][fn][1]);
                    mma8(acc[fm][fn], af[1][fm], bf[0][fn][0], bf[0][fn][1]);
                    mma8(acc[fm][fn], af[0][fm], bf[1][fn][0], bf[1][fn][1]);
                }
        }
        __syncthreads();
    }

    #pragma unroll
    for (int fn = 0; fn < 4; fn++) {
        const int col = n0 + wn * 32 + fn * 8 + 2 * tig;
        const float b0v = bias[col], b1v = bias[col + 1];
        #pragma unroll
        for (int fm = 0; fm < 4; fm++) {
            const int row = m0 + wm * 64 + fm * 16 + g;
            #pragma unroll
            for (int half = 0; half < 2; half++) {
                const int r = row + half * 8;
                *(float2*)&out[(size_t)r * E + col] =
                    make_float2(acc[fm][fn][half * 2 + 0] + b0v,
                                acc[fm][fn][half * 2 + 1] + b1v);
            }
        }
    }
}

// ---------------------------------------------------------------------------
// Flash attention, 3xTF32.
// CTA: 128 q-rows, K tiles of 32.  8 warps, each owns 16 full q-rows.
// smem words: K hi/lo [32][76]x2, V hi/lo [32][72]x2, Q/P region [9728]
//   (Q staged per-plane at pitch 76, then region reused as per-warp
//    P hi/lo [16][36] x2 planes).
// ---------------------------------------------------------------------------
#define KH_OFF 0
#define KL_OFF 2432
#define VH_OFF 4864
#define VL_OFF 7168
#define QP_OFF 9472
#define ATT_SMEM_WORDS 19200   // 76,800 B

__global__ __launch_bounds__(256)
void attn_kernel(const float* __restrict__ pb, const float* __restrict__ coeff)
{
    extern __shared__ unsigned sm[];

    const int tid = threadIdx.x;
    const int w = tid >> 5, lane = tid & 31, g = lane >> 2, tig = lane & 3;
    const int b = blockIdx.z, h = blockIdx.y, q0 = blockIdx.x * 128;

    const float* Qg = g_Q + (size_t)(b * H + h) * S * D;
    const float* Kg = g_K + (size_t)(b * H + h) * S * D;
    const float* Vg = g_V + (size_t)(b * H + h) * S * D;
    const float* kbp = g_kbias + (size_t)(b * H + h) * S;

    // ---- stage Q plane-by-plane through the QP region, grab fragments ----
    unsigned qa[2][8][4];
    #pragma unroll
    for (int p = 0; p < 2; p++) {
        #pragma unroll
        for (int t = 0; t < 8; t++) {
            int i = tid + t * 256;
            int r = i >> 4, c4 = (i & 15) << 2;
            float4 v = *(const float4*)(Qg + (size_t)(q0 + r) * D + c4);
            unsigned* dst = &sm[QP_OFF + r * 76 + c4];
            unsigned hi, lo;
            splt(v.x, hi, lo); dst[0] = p ? lo : hi;
            splt(v.y, hi, lo); dst[1] = p ? lo : hi;
            splt(v.z, hi, lo); dst[2] = p ? lo : hi;
            splt(v.w, hi, lo); dst[3] = p ? lo : hi;
        }
        __syncthreads();
        const int qb = QP_OFF + (w * 16 + g) * 76;
        #pragma unroll
        for (int kk = 0; kk < 8; kk++) {
            qa[p][kk][0] = sm[qb + kk * 8 + tig];
            qa[p][kk][1] = sm[qb + 8 * 76 + kk * 8 + tig];
            qa[p][kk][2] = sm[qb + kk * 8 + tig + 4];
            qa[p][kk][3] = sm[qb + 8 * 76 + kk * 8 + tig + 4];
        }
        __syncthreads();
    }

    const float coeff_h = coeff[h];
    float rowb[2];
    rowb[0] = coeff_h * pb[b * S + q0 + w * 16 + g];
    rowb[1] = coeff_h * pb[b * S + q0 + w * 16 + g + 8];

    float mi[2] = {-1e30f, -1e30f}, li[2] = {0.0f, 0.0f};
    float o[8][4];
    #pragma unroll
    for (int nf = 0; nf < 8; nf++)
        #pragma unroll
        for (int c = 0; c < 4; c++) o[nf][c] = 0.0f;

    const int psH = QP_OFF + w * 1152;        // P hi: 16 x 36
    const int psL = psH + 576;                // P lo: 16 x 36

    for (int k0 = 0; k0 < S; k0 += 32) {
        // ---- load K,V tiles, split hi/lo ----
        #pragma unroll
        for (int t = 0; t < 2; t++) {
            int i = tid + t * 256;
            int r = i >> 4, c4 = (i & 15) << 2;
            float4 kv = *(const float4*)(Kg + (size_t)(k0 + r) * D + c4);
            unsigned* kh = &sm[KH_OFF + r * 76 + c4];
            unsigned* kl = &sm[KL_OFF + r * 76 + c4];
            splt(kv.x, kh[0], kl[0]); splt(kv.y, kh[1], kl[1]);
            splt(kv.z, kh[2], kl[2]); splt(kv.w, kh[3], kl[3]);
            float4 vv = *(const float4*)(Vg + (size_t)(k0 + r) * D + c4);
            unsigned* vh = &sm[VH_OFF + r * 72 + c4];
            unsigned* vl = &sm[VL_OFF + r * 72 + c4];
            splt(vv.x, vh[0], vl[0]); splt(vv.y, vh[1], vl[1]);
            splt(vv.z, vh[2], vl[2]); splt(vv.w, vh[3], vl[3]);
        }
        __syncthreads();

        // ---- S = Q K^T (16 q x 32 k per warp), 3xTF32 ----
        float sc[4][4];
        #pragma unroll
        for (int fn = 0; fn < 4; fn++)
            #pragma unroll
            for (int c = 0; c < 4; c++) sc[fn][c] = 0.0f;

        #pragma unroll
        for (int kk = 0; kk < 8; kk++) {
            #pragma unroll
            for (int fn = 0; fn < 4; fn++) {
                int kb = (fn * 8 + g) * 76 + kk * 8 + tig;
                unsigned kh0 = sm[KH_OFF + kb], kh1 = sm[KH_OFF + kb + 4];
                unsigned kl0 = sm[KL_OFF + kb], kl1 = sm[KL_OFF + kb + 4];
                mma8(sc[fn], qa[0][kk], kh0, kh1);
                mma8(sc[fn], qa[1][kk], kh0, kh1);
                mma8(sc[fn], qa[0][kk], kl0, kl1);
            }
        }

        // ---- scale + rel-pos bias + mask ----
        #pragma unroll
        for (int fn = 0; fn < 4; fn++) {
            int c = k0 + fn * 8 + 2 * tig;
            float cb0 = kbp[c], cb1 = kbp[c + 1];
            sc[fn][0] = sc[fn][0] * 0.125f + rowb[0] + cb0;
            sc[fn][1] = sc[fn][1] * 0.125f + rowb[0] + cb1;
            sc[fn][2] = sc[fn][2] * 0.125f + rowb[1] + cb0;
            sc[fn][3] = sc[fn][3] * 0.125f + rowb[1] + cb1;
        }

        // ---- online softmax; P stored split hi/lo ----
        #pragma unroll
        for (int rh = 0; rh < 2; rh++) {
            float tm = -1e30f;
            #pragma unroll
            for (int fn = 0; fn < 4; fn++)
                tm = fmaxf(tm, fmaxf(sc[fn][2 * rh], sc[fn][2 * rh + 1]));
            tm = fmaxf(tm, __shfl_xor_sync(0xffffffffu, tm, 1));
            tm = fmaxf(tm, __shfl_xor_sync(0xffffffffu, tm, 2));
            float mnew = fmaxf(fmaxf(mi[rh], tm), -1e20f);
            float psum = 0.0f;
            const int pro = (g + rh * 8) * 36;
            #pragma unroll
            for (int fn = 0; fn < 4; fn++) {
                float p0 = __expf(sc[fn][2 * rh] - mnew);
                float p1 = __expf(sc[fn][2 * rh + 1] - mnew);
                psum += p0 + p1;
                unsigned hi, lo;
                splt(p0, hi, lo);
                sm[psH + pro + fn * 8 + 2 * tig] = hi;
                sm[psL + pro + fn * 8 + 2 * tig] = lo;
                splt(p1, hi, lo);
                sm[psH + pro + fn * 8 + 2 * tig + 1] = hi;
                sm[psL + pro + fn * 8 + 2 * tig + 1] = lo;
            }
            psum += __shfl_xor_sync(0xffffffffu, psum, 1);
            psum += __shfl_xor_sync(0xffffffffu, psum, 2);
            float scale = __expf(mi[rh] - mnew);
            li[rh] = li[rh] * scale + psum;
            mi[rh] = mnew;
            #pragma unroll
            for (int nf = 0; nf < 8; nf++) {
                o[nf][2 * rh]     *= scale;
                o[nf][2 * rh + 1] *= scale;
            }
        }
        __syncwarp();

        // ---- O += P V, 3xTF32 ----
        #pragma unroll
        for (int ks = 0; ks < 4; ks++) {
            unsigned pah[4], pal[4];
            pah[0] = sm[psH + g * 36 + ks * 8 + tig];
            pah[1] = sm[psH + (g + 8) * 36 + ks * 8 + tig];
            pah[2] = sm[psH + g * 36 + ks * 8 + tig + 4];
            pah[3] = sm[psH + (g + 8) * 36 + ks * 8 + tig + 4];
            pal[0] = sm[psL + g * 36 + ks * 8 + tig];
            pal[1] = sm[psL + (g + 8) * 36 + ks * 8 + tig];
            pal[2] = sm[psL + g * 36 + ks * 8 + tig + 4];
            pal[3] = sm[psL + (g + 8) * 36 + ks * 8 + tig + 4];
            #pragma unroll
            for (int nf = 0; nf < 8; nf++) {
                int vb0i = (ks * 8 + tig) * 72 + nf * 8 + g;
                int vb1i = (ks * 8 + tig + 4) * 72 + nf * 8 + g;
                unsigned vh0 = sm[VH_OFF + vb0i], vh1 = sm[VH_OFF + vb1i];
                unsigned vl0 = sm[VL_OFF + vb0i], vl1 = sm[VL_OFF + vb1i];
                mma8(o[nf], pah, vh0, vh1);
                mma8(o[nf], pal, vh0, vh1);
                mma8(o[nf], pah, vl0, vl1);
            }
        }
        __syncthreads();
    }

    // ---- normalize + store to [B,S,E] ----
    const float inv0 = 1.0f / li[0], inv1 = 1.0f / li[1];
    const int qg = q0 + w * 16 + g;
    #pragma unroll
    for (int nf = 0; nf < 8; nf++) {
        int d = nf * 8 + 2 * tig;
        *(float2*)&g_att[(size_t)(b * S + qg) * E + h * D + d] =
            make_float2(o[nf][0] * inv0, o[nf][1] * inv0);
        *(float2*)&g_att[(size_t)(b * S + qg + 8) * E + h * D + d] =
            make_float2(o[nf][2] * inv1, o[nf][3] * inv1);
    }
}

// ---------------------------------------------------------------------------
extern "C" void kernel_launch(void* const* d_in, const int* in_sizes, int n_in,
                              void* d_out, int out_size)
{
    const float* query = (const float*)d_in[0];
    const float* key   = (const float*)d_in[1];
    const float* value = (const float*)d_in[2];
    const float* pb    = (const float*)d_in[3];
    const unsigned char* mask = (const unsigned char*)d_in[4];
    const float* wq_w = (const float*)d_in[5];
    const float* wq_b = (const float*)d_in[6];
    const float* wk_w = (const float*)d_in[7];
    const float* wk_b = (const float*)d_in[8];
    const float* wv_w = (const float*)d_in[9];
    const float* wv_b = (const float*)d_in[10];
    const float* fc_w = (const float*)d_in[11];
    const float* fc_b = (const float*)d_in[12];
    const float* coeff = (const float*)d_in[13];
    float* out = (float*)d_out;

    const int attn_smem = ATT_SMEM_WORDS * (int)sizeof(unsigned);  // 76,800 B
    cudaFuncSetAttribute(attn_kernel,
                         cudaFuncAttributeMaxDynamicSharedMemorySize, attn_smem);

    mask_prep_kernel<<<1, 256>>>(mask);
    kbias_kernel<<<(B * H * S) / 256, 256>>>(pb, coeff);

    dim3 g1(E / 128, BSZ / 128, 3);   // (6, 32, 3)
    qkv_kernel<<<g1, 256>>>(query, key, value, wq_w, wk_w, wv_w,
                            wq_b, wk_b, wv_b);

    dim3 g2(S / 128, H, B);           // (16, 12, 2)
    attn_kernel<<<g2, 256, attn_smem>>>(pb, coeff);

    dim3 g3(E / 128, BSZ / 128);      // (6, 32)
    oproj_kernel<<<g3, 256>>>(fc_w, fc_b, out);
}